// round 1
// baseline (speedup 1.0000x reference)
#include <cuda_runtime.h>
#include <cuda_bf16.h>
#include <math.h>

// Problem dims
#define SEQ    512
#define BATCH  128
#define INDIM  256
#define HID    512
#define ODIM   128

#define NGROUPS 16          // batch groups (8 rows each)
#define NSLICES 8           // hidden slices (64 cols each)
#define BG      (BATCH / NGROUPS)   // 8 rows per group
#define NC      (HID / NSLICES)     // 64 cols per slice

// Scratch: xh written by K1, overwritten in-place by h_s during recurrence,
// then consumed by K3. [SEQ][BATCH][HID] fp32 = 134 MB static device array.
__device__ float g_buf[(size_t)SEQ * BATCH * HID];
// One flag per (step, group): counts CTAs of the group that finished step s.
__device__ int g_flags[SEQ * NGROUPS];

// ---------------------------------------------------------------------------
// Zero the flags each launch (deterministic across graph replays).
// ---------------------------------------------------------------------------
__global__ void zero_flags_kernel() {
    int i = blockIdx.x * blockDim.x + threadIdx.x;
    if (i < SEQ * NGROUPS) g_flags[i] = 0;
}

// ---------------------------------------------------------------------------
// Tiled fp32 GEMM with bias: C[M,N] = A[M,K] @ B[K,N] + bias[N]
// BM=128, BN=64, BK=16, TM=8, TN=4, 256 threads.
// ---------------------------------------------------------------------------
template <int BM, int BN, int BK, int TM, int TN>
__global__ void __launch_bounds__(256, 2)
sgemm_bias_kernel(const float* __restrict__ A,
                  const float* __restrict__ B,
                  const float* __restrict__ bias,
                  float* __restrict__ C,
                  int M, int N, int K) {
    __shared__ float sA[BK][BM + 4];   // A tile stored transposed, padded
    __shared__ float sB[BK][BN];

    const int tid = threadIdx.x;
    const int tx = tid % (BN / TN);    // 16 (N direction)
    const int ty = tid / (BN / TN);    // 16 (M direction)
    const int m0 = blockIdx.y * BM;
    const int n0 = blockIdx.x * BN;

    float acc[TM][TN];
#pragma unroll
    for (int i = 0; i < TM; i++)
#pragma unroll
        for (int j = 0; j < TN; j++) acc[i][j] = 0.0f;

    for (int k0 = 0; k0 < K; k0 += BK) {
        // Load A tile (BM x BK) as float4, store transposed into sA[k][m]
#pragma unroll
        for (int i = 0; i < (BM * BK) / (256 * 4); ++i) {
            int idx = tid + i * 256;            // float4 index
            int r   = idx / (BK / 4);           // row within tile
            int kq  = (idx % (BK / 4)) * 4;     // k offset (multiple of 4)
            float4 v = *(const float4*)&A[(size_t)(m0 + r) * K + k0 + kq];
            sA[kq + 0][r] = v.x;
            sA[kq + 1][r] = v.y;
            sA[kq + 2][r] = v.z;
            sA[kq + 3][r] = v.w;
        }
        // Load B tile (BK x BN) as float4
#pragma unroll
        for (int i = 0; i < (BK * BN) / (256 * 4); ++i) {
            int idx = tid + i * 256;
            int r   = idx / (BN / 4);
            int cq  = (idx % (BN / 4)) * 4;
            *(float4*)&sB[r][cq] =
                *(const float4*)&B[(size_t)(k0 + r) * N + n0 + cq];
        }
        __syncthreads();

#pragma unroll
        for (int kk = 0; kk < BK; ++kk) {
            float ra[TM], rb[TN];
#pragma unroll
            for (int i = 0; i < TM; i++) ra[i] = sA[kk][ty * TM + i];
#pragma unroll
            for (int j = 0; j < TN; j++) rb[j] = sB[kk][tx * TN + j];
#pragma unroll
            for (int i = 0; i < TM; i++)
#pragma unroll
                for (int j = 0; j < TN; j++) acc[i][j] += ra[i] * rb[j];
        }
        __syncthreads();
    }

#pragma unroll
    for (int i = 0; i < TM; i++) {
        int row = m0 + ty * TM + i;
#pragma unroll
        for (int j = 0; j < TN; j++) {
            int col = n0 + tx * TN + j;
            C[(size_t)row * N + col] = acc[i][j] + bias[col];
        }
    }
}

// ---------------------------------------------------------------------------
// Persistent recurrence kernel.
// Grid: 128 CTAs = NGROUPS(16 batch groups) x NSLICES(8 hidden slices).
// CTA (g,c): rows [g*8, g*8+8), cols [c*64, c*64+64).
// W_hh[:, slice] cached in SMEM (fp32, 128 KB). Per step:
//   wait group flag[s-1] -> stage h_prev[8][512] to SMEM ->
//   acc = xh (from g_buf[s]) + h_prev @ Wslice -> tanh -> write g_buf[s]
//   -> fence -> bump flag[s].
// All 128 CTAs are co-resident (1 CTA/SM, 148 SMs), so spin-wait is safe.
// ---------------------------------------------------------------------------
#define REC_SMEM_BYTES ((HID * NC + BG * HID) * 4)   // 128KB W + 16KB h

__global__ void __launch_bounds__(256, 1)
rnn_recur_kernel(const float* __restrict__ Whh) {
    extern __shared__ float sm[];
    float* sW = sm;                 // [HID][NC]
    float* sH = sm + HID * NC;      // [BG][HID]

    const int tid = threadIdx.x;
    const int g = blockIdx.x >> 3;         // batch group 0..15
    const int c = blockIdx.x & 7;          // hidden slice 0..7
    const int colBase = c * NC;
    const int rowBase = g * BG;

    // Cache W_hh[:, colBase..colBase+63] in SMEM (one-time).
    for (int idx = tid; idx < HID * NC / 2; idx += 256) {
        int r  = idx / (NC / 2);
        int cc = (idx % (NC / 2)) * 2;
        float2 v = *(const float2*)&Whh[(size_t)r * HID + colBase + cc];
        *(float2*)&sW[r * NC + cc] = v;
    }
    // h_0 = 0
    for (int idx = tid; idx < BG * HID; idx += 256) sH[idx] = 0.0f;
    __syncthreads();

    const int b = tid >> 5;                // 0..7  (batch row within group)
    const int j = tid & 31;                // 0..31 (column pair)
    const int row = rowBase + b;
    const float2* sWf2 = (const float2*)sW;

    for (int s = 0; s < SEQ; ++s) {
        if (s > 0) {
            if (tid == 0) {
                while (atomicAdd(&g_flags[(s - 1) * NGROUPS + g], 0) < NSLICES) { }
            }
            __syncthreads();
            // Stage h_{s-1}[rowBase..rowBase+8][:] -> SMEM (coalesced float4)
            const float4* src = (const float4*)
                &g_buf[(size_t)(s - 1) * BATCH * HID + (size_t)rowBase * HID];
            float4* dst = (float4*)sH;
#pragma unroll
            for (int i = 0; i < (BG * HID) / (4 * 256); ++i)
                dst[tid + i * 256] = src[tid + i * 256];
            __syncthreads();
        }

        // acc starts at xh (precomputed into g_buf[s])
        float2 acc = *(const float2*)
            &g_buf[(size_t)s * BATCH * HID + (size_t)row * HID + colBase + 2 * j];

        const float* hrow = &sH[b * HID];
#pragma unroll 8
        for (int k = 0; k < HID; ++k) {
            float hv = hrow[k];
            float2 w = sWf2[k * (NC / 2) + j];
            acc.x += hv * w.x;
            acc.y += hv * w.y;
        }

        float2 hout;
        hout.x = tanhf(acc.x);
        hout.y = tanhf(acc.y);
        *(float2*)&g_buf[(size_t)s * BATCH * HID + (size_t)row * HID + colBase + 2 * j] = hout;

        __threadfence();
        __syncthreads();
        if (tid == 0) atomicAdd(&g_flags[s * NGROUPS + g], 1);
    }
}

// ---------------------------------------------------------------------------
// kernel_launch
// Inputs (metadata order): x[512,128,256], W_xh[256,512], W_hh[512,512],
//                          W_hy[512,128], b_h[512], b_y[128]
// Output: out[512,128,128] fp32
// ---------------------------------------------------------------------------
extern "C" void kernel_launch(void* const* d_in, const int* in_sizes, int n_in,
                              void* d_out, int out_size) {
    const float* x   = (const float*)d_in[0];
    const float* Wxh = (const float*)d_in[1];
    const float* Whh = (const float*)d_in[2];
    const float* Why = (const float*)d_in[3];
    const float* bh  = (const float*)d_in[4];
    const float* by  = (const float*)d_in[5];
    float* out = (float*)d_out;

    float* buf = nullptr;
    cudaGetSymbolAddress((void**)&buf, g_buf);

    cudaFuncSetAttribute(rnn_recur_kernel,
                         cudaFuncAttributeMaxDynamicSharedMemorySize,
                         REC_SMEM_BYTES);

    // 0) zero the per-step flags (deterministic per replay)
    zero_flags_kernel<<<(SEQ * NGROUPS + 255) / 256, 256>>>();

    // 1) xh = x @ W_xh + b_h   -> g_buf   [65536,256]@[256,512]
    {
        dim3 grid(HID / 64, (SEQ * BATCH) / 128);
        sgemm_bias_kernel<128, 64, 16, 8, 4><<<grid, 256>>>(
            x, Wxh, bh, buf, SEQ * BATCH, HID, INDIM);
    }

    // 2) recurrence: h_s = tanh(xh_s + h_{s-1} @ W_hh), in-place in g_buf
    rnn_recur_kernel<<<NGROUPS * NSLICES, 256, REC_SMEM_BYTES>>>(Whh);

    // 3) out = hs @ W_hy + b_y   [65536,512]@[512,128]
    {
        dim3 grid(ODIM / 64, (SEQ * BATCH) / 128);
        sgemm_bias_kernel<128, 64, 16, 8, 4><<<grid, 256>>>(
            buf, Why, by, out, SEQ * BATCH, ODIM, HID);
    }
}

// round 2
// speedup vs baseline: 1.6705x; 1.6705x over previous
#include <cuda_runtime.h>
#include <cuda_bf16.h>
#include <math.h>

// Problem dims
#define SEQ    512
#define BATCH  128
#define INDIM  256
#define HID    512
#define ODIM   128

#define NGROUPS 16          // batch groups (8 rows each)
#define NSLICES 8           // hidden slices (64 cols each)
#define BG      (BATCH / NGROUPS)   // 8 rows per group
#define NC      (HID / NSLICES)     // 64 cols per slice
#define SWS     (HID + 4)           // padded k-stride of transposed W slice

// Scratch: xh written by K1, overwritten in-place by h_s during recurrence,
// then consumed by K3. [SEQ][BATCH][HID] fp32 = 134 MB static device array.
__device__ float g_buf[(size_t)SEQ * BATCH * HID];
// One flag per (step, group): counts CTAs of the group that finished step s.
__device__ int g_flags[SEQ * NGROUPS];

typedef unsigned long long ull;

__device__ __forceinline__ ull fma2(ull a, ull b, ull c) {
    ull d;
    asm("fma.rn.f32x2 %0, %1, %2, %3;" : "=l"(d) : "l"(a), "l"(b), "l"(c));
    return d;
}
__device__ __forceinline__ void upk(ull v, float& x, float& y) {
    asm("mov.b64 {%0,%1}, %2;" : "=f"(x), "=f"(y) : "l"(v));
}
__device__ __forceinline__ int ldacq(const int* p) {
    int v;
    asm volatile("ld.acquire.gpu.b32 %0, [%1];" : "=r"(v) : "l"(p));
    return v;
}

// ---------------------------------------------------------------------------
// Zero the flags each launch (deterministic across graph replays).
// ---------------------------------------------------------------------------
__global__ void zero_flags_kernel() {
    int i = blockIdx.x * blockDim.x + threadIdx.x;
    if (i < SEQ * NGROUPS) g_flags[i] = 0;
}

// ---------------------------------------------------------------------------
// Tiled fp32 GEMM with bias: C[M,N] = A[M,K] @ B[K,N] + bias[N]
// ---------------------------------------------------------------------------
template <int BM, int BN, int BK, int TM, int TN>
__global__ void __launch_bounds__(256, 2)
sgemm_bias_kernel(const float* __restrict__ A,
                  const float* __restrict__ B,
                  const float* __restrict__ bias,
                  float* __restrict__ C,
                  int M, int N, int K) {
    __shared__ float sA[BK][BM + 4];   // A tile stored transposed, padded
    __shared__ float sB[BK][BN];

    const int tid = threadIdx.x;
    const int tx = tid % (BN / TN);
    const int ty = tid / (BN / TN);
    const int m0 = blockIdx.y * BM;
    const int n0 = blockIdx.x * BN;

    float acc[TM][TN];
#pragma unroll
    for (int i = 0; i < TM; i++)
#pragma unroll
        for (int j = 0; j < TN; j++) acc[i][j] = 0.0f;

    for (int k0 = 0; k0 < K; k0 += BK) {
#pragma unroll
        for (int i = 0; i < (BM * BK) / (256 * 4); ++i) {
            int idx = tid + i * 256;
            int r   = idx / (BK / 4);
            int kq  = (idx % (BK / 4)) * 4;
            float4 v = *(const float4*)&A[(size_t)(m0 + r) * K + k0 + kq];
            sA[kq + 0][r] = v.x;
            sA[kq + 1][r] = v.y;
            sA[kq + 2][r] = v.z;
            sA[kq + 3][r] = v.w;
        }
#pragma unroll
        for (int i = 0; i < (BK * BN) / (256 * 4); ++i) {
            int idx = tid + i * 256;
            int r   = idx / (BN / 4);
            int cq  = (idx % (BN / 4)) * 4;
            *(float4*)&sB[r][cq] =
                *(const float4*)&B[(size_t)(k0 + r) * N + n0 + cq];
        }
        __syncthreads();

#pragma unroll
        for (int kk = 0; kk < BK; ++kk) {
            float ra[TM], rb[TN];
#pragma unroll
            for (int i = 0; i < TM; i++) ra[i] = sA[kk][ty * TM + i];
#pragma unroll
            for (int j = 0; j < TN; j++) rb[j] = sB[kk][tx * TN + j];
#pragma unroll
            for (int i = 0; i < TM; i++)
#pragma unroll
                for (int j = 0; j < TN; j++) acc[i][j] += ra[i] * rb[j];
        }
        __syncthreads();
    }

#pragma unroll
    for (int i = 0; i < TM; i++) {
        int row = m0 + ty * TM + i;
#pragma unroll
        for (int j = 0; j < TN; j++) {
            int col = n0 + tx * TN + j;
            C[(size_t)row * N + col] = acc[i][j] + bias[col];
        }
    }
}

// ---------------------------------------------------------------------------
// Persistent recurrence kernel (optimized).
// Grid: 128 CTAs = 16 batch groups x 8 hidden slices; all co-resident.
// CTA (g,c): rows [g*8, g*8+8), cols [c*64, c*64+64).
//
// Per-CTA SMEM: sW = W_hh slice TRANSPOSED [NC][HID+4] fp32 (129 KB),
//               sH = h_prev [8][512] (16 KB).
// Thread map: warp w = batch row w; lane j handles cols j and j+32.
// Inner product uses packed fma.rn.f32x2 over k-pairs; all SMEM reads LDS.128
// conflict-free; h reads are warp-uniform broadcasts.
// xh[s+1] is prefetched into registers during step s compute (hides DRAM).
// Publish: one-thread __threadfence + relaxed atomic; wait: ld.acquire poll.
// ---------------------------------------------------------------------------
#define REC_SMEM_BYTES ((NC * SWS + BG * HID) * 4)

__global__ void __launch_bounds__(256, 1)
rnn_recur_kernel(const float* __restrict__ Whh) {
    extern __shared__ float sm[];
    float* sW = sm;                    // [NC][SWS] (transposed: [col][k])
    float* sH = sm + NC * SWS;         // [BG][HID]

    const int tid = threadIdx.x;
    const int g = blockIdx.x >> 3;     // batch group 0..15
    const int c = blockIdx.x & 7;      // hidden slice 0..7
    const int colBase = c * NC;
    const int rowBase = g * BG;

    // Cache W_hh[:, colBase..colBase+63] transposed into SMEM (one-time).
    for (int idx = tid; idx < HID * NC; idx += 256) {
        int k  = idx >> 6;             // 0..511
        int cc = idx & 63;             // 0..63  (coalesced global read)
        sW[cc * SWS + k] = Whh[(size_t)k * HID + colBase + cc];
    }
    __syncthreads();

    const int b = tid >> 5;            // warp id == batch row within group
    const int j = tid & 31;
    const size_t rowOff = (size_t)(rowBase + b) * HID + colBase;

    const ulonglong2* hp = (const ulonglong2*)(sH + b * HID);
    const ulonglong2* wA = (const ulonglong2*)(sW + (size_t)j * SWS);
    const ulonglong2* wB = (const ulonglong2*)(sW + (size_t)(j + 32) * SWS);

    // Preload xh[0]
    float xa0, xa1;
    {
        const float* gx = g_buf + rowOff;
        xa0 = gx[j];
        xa1 = gx[j + 32];
    }

    for (int s = 0; s < SEQ; ++s) {
        if (s > 0) {
            if (tid == 0) {
                while (ldacq(&g_flags[(s - 1) * NGROUPS + g]) < NSLICES) { }
            }
            __syncthreads();
            // Stage h_{s-1}[rowBase..rowBase+8][:] -> SMEM (1024 float4)
            const float4* src = (const float4*)
                (g_buf + (size_t)(s - 1) * BATCH * HID + (size_t)rowBase * HID);
            float4* dst = (float4*)sH;
            dst[tid]       = src[tid];
            dst[tid + 256] = src[tid + 256];
            dst[tid + 512] = src[tid + 512];
            dst[tid + 768] = src[tid + 768];
            __syncthreads();
        }

        // Prefetch xh for the NEXT step (consumed ~2K cycles later).
        float pf0 = 0.0f, pf1 = 0.0f;
        if (s + 1 < SEQ) {
            const float* gx = g_buf + (size_t)(s + 1) * BATCH * HID + rowOff;
            pf0 = gx[j];
            pf1 = gx[j + 32];
        }

        float va = xa0, vb = xa1;
        if (s > 0) {
            ull aa0 = 0, aa1 = 0, ab0 = 0, ab1 = 0;
#pragma unroll 8
            for (int i = 0; i < HID / 4; i += 2) {   // i in ulonglong2 units
                ulonglong2 h0 = hp[i], h1 = hp[i + 1];
                ulonglong2 a0 = wA[i], a1 = wA[i + 1];
                ulonglong2 b0 = wB[i], b1 = wB[i + 1];
                aa0 = fma2(h0.x, a0.x, aa0);
                aa1 = fma2(h0.y, a0.y, aa1);
                ab0 = fma2(h0.x, b0.x, ab0);
                ab1 = fma2(h0.y, b0.y, ab1);
                aa0 = fma2(h1.x, a1.x, aa0);
                aa1 = fma2(h1.y, a1.y, aa1);
                ab0 = fma2(h1.x, b1.x, ab0);
                ab1 = fma2(h1.y, b1.y, ab1);
            }
            float x0, y0, x1, y1;
            upk(aa0, x0, y0); upk(aa1, x1, y1);
            va += (x0 + y0) + (x1 + y1);
            upk(ab0, x0, y0); upk(ab1, x1, y1);
            vb += (x0 + y0) + (x1 + y1);
        }

        float ha = tanhf(va);
        float hb = tanhf(vb);
        float* gh = g_buf + (size_t)s * BATCH * HID + rowOff;
        gh[j]      = ha;
        gh[j + 32] = hb;

        __syncthreads();
        if (tid == 0) {
            __threadfence();
            atomicAdd(&g_flags[s * NGROUPS + g], 1);
        }

        xa0 = pf0;
        xa1 = pf1;
    }
}

// ---------------------------------------------------------------------------
// kernel_launch
// Inputs: x[512,128,256], W_xh[256,512], W_hh[512,512],
//         W_hy[512,128], b_h[512], b_y[128]  -> out[512,128,128] fp32
// ---------------------------------------------------------------------------
extern "C" void kernel_launch(void* const* d_in, const int* in_sizes, int n_in,
                              void* d_out, int out_size) {
    const float* x   = (const float*)d_in[0];
    const float* Wxh = (const float*)d_in[1];
    const float* Whh = (const float*)d_in[2];
    const float* Why = (const float*)d_in[3];
    const float* bh  = (const float*)d_in[4];
    const float* by  = (const float*)d_in[5];
    float* out = (float*)d_out;

    float* buf = nullptr;
    cudaGetSymbolAddress((void**)&buf, g_buf);

    cudaFuncSetAttribute(rnn_recur_kernel,
                         cudaFuncAttributeMaxDynamicSharedMemorySize,
                         REC_SMEM_BYTES);

    // 0) zero the per-step flags (deterministic per replay)
    zero_flags_kernel<<<(SEQ * NGROUPS + 255) / 256, 256>>>();

    // 1) xh = x @ W_xh + b_h   -> g_buf
    {
        dim3 grid(HID / 64, (SEQ * BATCH) / 128);
        sgemm_bias_kernel<128, 64, 16, 8, 4><<<grid, 256>>>(
            x, Wxh, bh, buf, SEQ * BATCH, HID, INDIM);
    }

    // 2) recurrence: h_s = tanh(xh_s + h_{s-1} @ W_hh), in-place in g_buf
    rnn_recur_kernel<<<NGROUPS * NSLICES, 256, REC_SMEM_BYTES>>>(Whh);

    // 3) out = hs @ W_hy + b_y
    {
        dim3 grid(ODIM / 64, (SEQ * BATCH) / 128);
        sgemm_bias_kernel<128, 64, 16, 8, 4><<<grid, 256>>>(
            buf, Why, by, out, SEQ * BATCH, ODIM, HID);
    }
}